// round 13
// baseline (speedup 1.0000x reference)
#include <cuda_runtime.h>
#include <cuda_bf16.h>
#include <cuda_fp16.h>
#include <cstdint>

#define NN   100000
#define EE   3200000
#define DIN  512
#define DHID 128
#define DOUT 4

// ======================= device scratch (static) =======================
__device__ int    g_degi  [NN];
__device__ float  g_dis   [NN];
__device__ int    g_off   [NN];
__device__ int    g_cursor[NN];
__device__ int    g_bsum  [128];
__device__ int    g_boff  [128];
__device__ int    g_esrc  [EE];
__device__ __half g_hsh   [(size_t)NN * DHID];  // X@W1 (UNSCALED), fp16
__device__ float  g_hs2   [NN * DOUT];          // (h1@W2)*dis
__device__ __half g_wthi  [DHID * DIN];         // W1^T hi  [n][k], fp16
__device__ __half g_wtlo  [DHID * DIN];         // W1^T lo  [n][k], fp16 residual
__device__ int    g_is64;

// edge_index may arrive as int64 (reference dtype) or int32 (JAX x64 off).
__device__ __forceinline__ void load_edge(const void* ei, int e, int& s, int& d) {
    if (g_is64) {
        const long long* p = (const long long*)ei;
        s = (int)p[e];
        d = (int)p[(size_t)EE + e];
    } else {
        const int* p = (const int*)ei;
        s = p[e];
        d = p[EE + e];
    }
}

__device__ __forceinline__ uint32_t pack_h2(float a, float b) {
    __half2 h = __floats2half2_rn(a, b);
    return *(uint32_t*)&h;
}

__device__ __forceinline__ uint32_t smem_u32(const void* p) {
    uint32_t a;
    asm("{ .reg .u64 t; cvta.to.shared.u64 t, %1; cvt.u32.u64 %0, t; }"
        : "=r"(a) : "l"(p));
    return a;
}
#define LDSM_X4(r0, r1, r2, r3, addr) \
    asm volatile("ldmatrix.sync.aligned.m8n8.x4.shared.b16 {%0,%1,%2,%3}, [%4];" \
        : "=r"(r0), "=r"(r1), "=r"(r2), "=r"(r3) : "r"(addr))
#define CP16(dst, src) \
    asm volatile("cp.async.ca.shared.global [%0], [%1], 16;" :: "r"(dst), "l"(src))
#define CP_COMMIT() asm volatile("cp.async.commit_group;")
#define CP_WAIT0()  asm volatile("cp.async.wait_group 0;" ::: "memory")

// ===== init: detect idx width + zero degrees + W1 transpose/split (fp16) =====
__global__ void init_kernel(const int* __restrict__ ei32, const float* __restrict__ W1) {
    int idx = blockIdx.x * blockDim.x + threadIdx.x;
    if (idx == 0) {
        int all0 = 1;
        #pragma unroll
        for (int i = 1; i < 64; i += 2) all0 &= (ei32[i] == 0);
        g_is64 = all0;
    }
    if (idx < NN) g_degi[idx] = 0;
    if (idx < DHID * DIN) {
        int n = idx >> 9;
        int k = idx & 511;
        float w = W1[(size_t)k * DHID + n];
        __half h = __float2half_rn(w);
        g_wthi[idx] = h;
        g_wtlo[idx] = __float2half_rn(w - __half2float(h));
    }
}

__global__ void degree_kernel(const void* __restrict__ ei) {
    int e = (blockIdx.x * blockDim.x + threadIdx.x) * 2;
    if (e >= EE) return;
    if (g_is64) {
        const long long* p = (const long long*)ei;
        longlong2 v = *(const longlong2*)(p + EE + e);
        atomicAdd(&g_degi[(int)v.x], 1);
        atomicAdd(&g_degi[(int)v.y], 1);
    } else {
        const int* p = (const int*)ei;
        int2 v = *(const int2*)(p + EE + e);
        atomicAdd(&g_degi[v.x], 1);
        atomicAdd(&g_degi[v.y], 1);
    }
}

__global__ void dis_kernel() {
    int i = blockIdx.x * blockDim.x + threadIdx.x;
    if (i < NN) g_dis[i] = rsqrtf((float)g_degi[i] + 1.0f);
}

__global__ void scan1_kernel() {
    __shared__ int sh[1024];
    int t = threadIdx.x;
    int i = blockIdx.x * 1024 + t;
    int v = (i < NN) ? g_degi[i] : 0;
    sh[t] = v;
    __syncthreads();
    for (int d = 1; d < 1024; d <<= 1) {
        int add = (t >= d) ? sh[t - d] : 0;
        __syncthreads();
        sh[t] += add;
        __syncthreads();
    }
    if (i < NN) g_off[i] = sh[t] - v;
    if (t == 1023) g_bsum[blockIdx.x] = sh[1023];
}
__global__ void scan2_kernel(int nblk) {
    __shared__ int sh[128];
    int t = threadIdx.x;
    int v = (t < nblk) ? g_bsum[t] : 0;
    sh[t] = v;
    __syncthreads();
    for (int d = 1; d < 128; d <<= 1) {
        int add = (t >= d) ? sh[t - d] : 0;
        __syncthreads();
        sh[t] += add;
        __syncthreads();
    }
    if (t < nblk) g_boff[t] = sh[t] - v;
}
__global__ void scan3_kernel() {
    int i = blockIdx.x * blockDim.x + threadIdx.x;
    if (i >= NN) return;
    int o = g_off[i] + g_boff[i >> 10];
    g_off[i] = o;
    g_cursor[i] = o;
}
__global__ void fill_kernel(const void* __restrict__ ei) {
    int e = blockIdx.x * blockDim.x + threadIdx.x;
    if (e >= EE) return;
    int s, d;
    load_edge(ei, e, s, d);
    int pos = atomicAdd(&g_cursor[d], 1);
    g_esrc[pos] = s;
}

// ======================= GEMM1 via mma.sync fp16 (A single, W split) ===============
// CTA: 128(M) x 128(N), 512 threads = 16 warps 4(m) x 4(n); warp tile 32 x 32.
// fp16 split: A = fp16(X), W = Whi + Wlo (both fp16). TWO passes: A*Whi + A*Wlo.
// Epilogue writes UNSCALED hs (dis applied at gather) -> no dependency on degree.

#define SPITCH 40
#define OFF_A   0
#define OFF_BHI 5120
#define OFF_BLO 10240
#define BUF_ELEMS 15360
#define BUF_BYTES (BUF_ELEMS * 2)           // 30720
#define GEMM_SMEM_BYTES (2 * BUF_BYTES)     // 61440

__device__ __forceinline__ void mma_f16(float* d, const uint32_t* a, const uint32_t* b) {
    asm volatile(
        "mma.sync.aligned.m16n8k16.row.col.f32.f16.f16.f32 "
        "{%0,%1,%2,%3}, {%4,%5,%6,%7}, {%8,%9}, {%0,%1,%2,%3};"
        : "+f"(d[0]), "+f"(d[1]), "+f"(d[2]), "+f"(d[3])
        : "r"(a[0]), "r"(a[1]), "r"(a[2]), "r"(a[3]), "r"(b[0]), "r"(b[1]));
}

__global__ void __launch_bounds__(512, 1) gemm1_mma_kernel(const float* __restrict__ X) {
    extern __shared__ __half sm[];
    const uint32_t sbase = smem_u32(sm);

    const int tid   = threadIdx.x;
    const int lane  = tid & 31;
    const int wid   = tid >> 5;
    const int warpM = wid & 3;
    const int warpN = wid >> 2;
    const int g     = lane >> 2;
    const int t     = lane & 3;
    const int mbase = blockIdx.x * 128;

    const int ar  = tid >> 2;
    const int aof = (tid & 3) << 3;
    const bool av = (mbase + ar) < NN;
    const float* xrow = X + (size_t)(mbase + ar) * DIN;
    const int bn  = tid >> 2;
    const int bof = (tid & 3) << 3;
    const uint32_t bhi0 = sbase + (uint32_t)(OFF_BHI + bn * SPITCH + bof) * 2;
    const uint32_t blo0 = sbase + (uint32_t)(OFF_BLO + bn * SPITCH + bof) * 2;

    const int arow = warpM * 32 + (lane & 15);
    const int acol = (lane >> 4) << 3;
    const int brow = warpN * 32 + ((lane >> 4) << 3) + (lane & 7);
    const int bcol = ((lane >> 3) & 1) << 3;

    float acc[2][4][4];
    #pragma unroll
    for (int mi = 0; mi < 2; mi++)
        #pragma unroll
        for (int ni = 0; ni < 4; ni++)
            #pragma unroll
            for (int q = 0; q < 4; q++) acc[mi][ni][q] = 0.0f;

    float4 xr0, xr1;
    xr0 = av ? *(const float4*)(xrow + aof)     : make_float4(0.f, 0.f, 0.f, 0.f);
    xr1 = av ? *(const float4*)(xrow + aof + 4) : make_float4(0.f, 0.f, 0.f, 0.f);
    CP16(bhi0, g_wthi + (size_t)bn * DIN + bof);
    CP16(blo0, g_wtlo + (size_t)bn * DIN + bof);
    CP_COMMIT();

    for (int kc = 0; kc < DIN / 32; kc++) {
        const uint32_t bufe = (uint32_t)(kc & 1) * BUF_ELEMS;
        const uint32_t bufb = bufe * 2;
        __half* pA = sm + bufe + OFF_A;

        {
            uint4 q;
            q.x = pack_h2(xr0.x, xr0.y);
            q.y = pack_h2(xr0.z, xr0.w);
            q.z = pack_h2(xr1.x, xr1.y);
            q.w = pack_h2(xr1.z, xr1.w);
            const int off = ar * SPITCH + aof;
            *(uint4*)&pA[off] = q;
        }
        if (kc + 1 < DIN / 32) {
            const int k1 = (kc + 1) * 32;
            xr0 = av ? *(const float4*)(xrow + k1 + aof)     : make_float4(0.f, 0.f, 0.f, 0.f);
            xr1 = av ? *(const float4*)(xrow + k1 + aof + 4) : make_float4(0.f, 0.f, 0.f, 0.f);
        }
        CP_WAIT0();
        __syncthreads();

        if (kc + 1 < DIN / 32) {
            const int k1 = (kc + 1) * 32;
            const uint32_t ob = (uint32_t)((kc + 1) & 1) * BUF_BYTES;
            CP16(bhi0 + ob, g_wthi + (size_t)bn * DIN + k1 + bof);
            CP16(blo0 + ob, g_wtlo + (size_t)bn * DIN + k1 + bof);
            CP_COMMIT();
        }

        #pragma unroll
        for (int kh = 0; kh < 2; kh++) {
            const int kk = kh * 16;
            uint32_t a[2][4];
            #pragma unroll
            for (int mi = 0; mi < 2; mi++) {
                const uint32_t ab = sbase + bufb +
                    (uint32_t)((arow + mi * 16) * SPITCH + kk + acol) * 2;
                LDSM_X4(a[mi][0], a[mi][1], a[mi][2], a[mi][3], ab + OFF_A * 2);
            }
            uint32_t bh[4][2], bl[4][2];
            #pragma unroll
            for (int nb = 0; nb < 2; nb++) {
                const uint32_t bb = sbase + bufb +
                    (uint32_t)((brow + nb * 16) * SPITCH + kk + bcol) * 2;
                LDSM_X4(bh[2 * nb][0], bh[2 * nb][1], bh[2 * nb + 1][0], bh[2 * nb + 1][1],
                        bb + OFF_BHI * 2);
                LDSM_X4(bl[2 * nb][0], bl[2 * nb][1], bl[2 * nb + 1][0], bl[2 * nb + 1][1],
                        bb + OFF_BLO * 2);
            }
            #pragma unroll
            for (int mi = 0; mi < 2; mi++)
                #pragma unroll
                for (int ni = 0; ni < 4; ni++) {
                    mma_f16(acc[mi][ni], a[mi], bh[ni]);
                    mma_f16(acc[mi][ni], a[mi], bl[ni]);
                }
        }
    }

    // ---- epilogue: write UNSCALED hs (fp16) ----
    #pragma unroll
    for (int mi = 0; mi < 2; mi++) {
        const int r0 = mbase + warpM * 32 + mi * 16 + g;
        const int r1 = r0 + 8;
        #pragma unroll
        for (int ni = 0; ni < 4; ni++) {
            const int n = warpN * 32 + ni * 8 + 2 * t;
            if (r0 < NN) {
                __half2 v = __floats2half2_rn(acc[mi][ni][0], acc[mi][ni][1]);
                *(__half2*)&g_hsh[(size_t)r0 * DHID + n] = v;
            }
            if (r1 < NN) {
                __half2 v = __floats2half2_rn(acc[mi][ni][2], acc[mi][ni][3]);
                *(__half2*)&g_hsh[(size_t)r1 * DHID + n] = v;
            }
        }
    }
}

// ===== CSR agg layer 1 (fp16 gather, dis applied at gather) + relu + fused GEMM2 ====
__global__ void __launch_bounds__(256) agg1_fused_kernel(const float* __restrict__ b1,
                                                         const float* __restrict__ W2) {
    int gw   = (blockIdx.x * blockDim.x + threadIdx.x) >> 5;
    int lane = threadIdx.x & 31;
    if (gw >= NN) return;
    int beg = g_off[gw];
    int end = beg + g_degi[gw];
    const uint2* hs = (const uint2*)g_hsh;
    const float dgw = g_dis[gw];

    float4 acc;
    {
        uint2 u = hs[(size_t)gw * 32 + lane];     // self term: dgw * hsu[gw]
        float2 p0 = __half22float2(*(__half2*)&u.x);
        float2 p1 = __half22float2(*(__half2*)&u.y);
        acc.x = dgw * p0.x; acc.y = dgw * p0.y; acc.z = dgw * p1.x; acc.w = dgw * p1.y;
    }
    for (int j0 = beg; j0 < end; j0 += 32) {
        int mj = j0 + lane;
        bool mv = (mj < end);
        int   sj = mv ? g_esrc[mj] : 0;
        float dj = mv ? g_dis[sj]  : 0.0f;
        int cnt = min(32, end - j0);
        int u = 0;
        for (; u + 8 <= cnt; u += 8) {
            int   si[8];
            float di[8];
            #pragma unroll
            for (int q = 0; q < 8; q++) {
                si[q] = __shfl_sync(0xFFFFFFFFu, sj, u + q);
                di[q] = __shfl_sync(0xFFFFFFFFu, dj, u + q);
            }
            uint2 uv[8];
            #pragma unroll
            for (int q = 0; q < 8; q++) uv[q] = hs[(size_t)si[q] * 32 + lane];
            #pragma unroll
            for (int q = 0; q < 8; q++) {
                float2 p0 = __half22float2(*(__half2*)&uv[q].x);
                float2 p1 = __half22float2(*(__half2*)&uv[q].y);
                acc.x = fmaf(di[q], p0.x, acc.x);
                acc.y = fmaf(di[q], p0.y, acc.y);
                acc.z = fmaf(di[q], p1.x, acc.z);
                acc.w = fmaf(di[q], p1.y, acc.w);
            }
        }
        for (; u < cnt; u++) {
            int   s = __shfl_sync(0xFFFFFFFFu, sj, u);
            float d = __shfl_sync(0xFFFFFFFFu, dj, u);
            uint2 uv = hs[(size_t)s * 32 + lane];
            float2 p0 = __half22float2(*(__half2*)&uv.x);
            float2 p1 = __half22float2(*(__half2*)&uv.y);
            acc.x = fmaf(d, p0.x, acc.x);
            acc.y = fmaf(d, p0.y, acc.y);
            acc.z = fmaf(d, p1.x, acc.z);
            acc.w = fmaf(d, p1.y, acc.w);
        }
    }
    float4 b = ((const float4*)b1)[lane];
    float4 h;
    h.x = fmaxf(acc.x * dgw + b.x, 0.f);
    h.y = fmaxf(acc.y * dgw + b.y, 0.f);
    h.z = fmaxf(acc.z * dgw + b.z, 0.f);
    h.w = fmaxf(acc.w * dgw + b.w, 0.f);
    float4 w0 = *(const float4*)(W2 + (4 * lane + 0) * 4);
    float4 w1 = *(const float4*)(W2 + (4 * lane + 1) * 4);
    float4 w2 = *(const float4*)(W2 + (4 * lane + 2) * 4);
    float4 w3 = *(const float4*)(W2 + (4 * lane + 3) * 4);
    float a0 = h.x * w0.x + h.y * w1.x + h.z * w2.x + h.w * w3.x;
    float a1 = h.x * w0.y + h.y * w1.y + h.z * w2.y + h.w * w3.y;
    float a2 = h.x * w0.z + h.y * w1.z + h.z * w2.z + h.w * w3.z;
    float a3 = h.x * w0.w + h.y * w1.w + h.z * w2.w + h.w * w3.w;
    #pragma unroll
    for (int o = 16; o; o >>= 1) {
        a0 += __shfl_xor_sync(0xFFFFFFFFu, a0, o);
        a1 += __shfl_xor_sync(0xFFFFFFFFu, a1, o);
        a2 += __shfl_xor_sync(0xFFFFFFFFu, a2, o);
        a3 += __shfl_xor_sync(0xFFFFFFFFu, a3, o);
    }
    if (lane == 0) {
        float4 v;
        v.x = a0 * dgw; v.y = a1 * dgw; v.z = a2 * dgw; v.w = a3 * dgw;
        *((float4*)g_hs2 + gw) = v;
    }
}

// ======================= CSR aggregation, layer 2 (fused bias) =======================
__global__ void agg2_csr_kernel(const float* __restrict__ b2, float* __restrict__ out) {
    int i = blockIdx.x * blockDim.x + threadIdx.x;
    if (i >= NN) return;
    int beg = g_off[i];
    int end = beg + g_degi[i];
    const float4* h4 = (const float4*)g_hs2;
    float4 acc = h4[i];
    int j = beg;
    for (; j + 4 <= end; j += 4) {
        float4 v0 = h4[g_esrc[j]];
        float4 v1 = h4[g_esrc[j + 1]];
        float4 v2 = h4[g_esrc[j + 2]];
        float4 v3 = h4[g_esrc[j + 3]];
        acc.x += (v0.x + v1.x) + (v2.x + v3.x);
        acc.y += (v0.y + v1.y) + (v2.y + v3.y);
        acc.z += (v0.z + v1.z) + (v2.z + v3.z);
        acc.w += (v0.w + v1.w) + (v2.w + v3.w);
    }
    for (; j < end; j++) {
        float4 v = h4[g_esrc[j]];
        acc.x += v.x; acc.y += v.y; acc.z += v.z; acc.w += v.w;
    }
    float s = g_dis[i];
    float4 b = *(const float4*)b2;
    float4 v;
    v.x = acc.x * s + b.x;
    v.y = acc.y * s + b.y;
    v.z = acc.z * s + b.z;
    v.w = acc.w * s + b.w;
    *((float4*)out + i) = v;
}

// ======================= launch =======================
static cudaStream_t g_s2;
static cudaEvent_t  g_evA, g_evB;

extern "C" void kernel_launch(void* const* d_in, const int* in_sizes, int n_in,
                              void* d_out, int out_size) {
    const float* x  = (const float*)d_in[0];
    const void*  ei = d_in[1];
    const float* W1 = (const float*)d_in[2];
    const float* b1 = (const float*)d_in[3];
    const float* W2 = (const float*)d_in[4];
    const float* b2 = (const float*)d_in[5];
    float* out = (float*)d_out;

    // one-time setup on the first (uncaptured) correctness call
    static bool s_init = []() {
        cudaFuncSetAttribute(gemm1_mma_kernel,
                             cudaFuncAttributeMaxDynamicSharedMemorySize, GEMM_SMEM_BYTES);
        cudaStreamCreateWithFlags(&g_s2, cudaStreamNonBlocking);
        cudaEventCreateWithFlags(&g_evA, cudaEventDisableTiming);
        cudaEventCreateWithFlags(&g_evB, cudaEventDisableTiming);
        return true;
    }();
    (void)s_init;

    const int nblk_scan = (NN + 1023) / 1024;           // 98
    const int nblk_init = (NN + 255) / 256;

    // init on main stream, then fork: CSR-build chain on s2 || gemm1 on main.
    init_kernel<<<nblk_init, 256>>>((const int*)ei, W1);
    cudaEventRecord(g_evA, 0);
    cudaStreamWaitEvent(g_s2, g_evA, 0);

    degree_kernel<<<(EE / 2 + 255) / 256, 256, 0, g_s2>>>(ei);
    dis_kernel   <<<(NN + 255) / 256, 256, 0, g_s2>>>();
    // gemm1 is launch index 3 -> stays in the ncu capture slot
    gemm1_mma_kernel<<<(NN + 127) / 128, 512, GEMM_SMEM_BYTES>>>(x);
    scan1_kernel <<<nblk_scan, 1024, 0, g_s2>>>();
    scan2_kernel <<<1, 128, 0, g_s2>>>(nblk_scan);
    scan3_kernel <<<(NN + 255) / 256, 256, 0, g_s2>>>();
    fill_kernel  <<<(EE + 255) / 256, 256, 0, g_s2>>>(ei);
    cudaEventRecord(g_evB, g_s2);
    cudaStreamWaitEvent(0, g_evB, 0);

    agg1_fused_kernel<<<(NN * 32 + 255) / 256, 256>>>(b1, W2);
    agg2_csr_kernel  <<<(NN + 255) / 256, 256>>>(b2, out);
}

// round 14
// speedup vs baseline: 1.0449x; 1.0449x over previous
#include <cuda_runtime.h>
#include <cuda_bf16.h>
#include <cuda_fp16.h>
#include <cstdint>

#define NN   100000
#define EE   3200000
#define DIN  512
#define DHID 128
#define DOUT 4

// ======================= device scratch (static) =======================
__device__ int    g_degi  [NN];
__device__ float  g_dis   [NN];
__device__ int    g_off   [NN];
__device__ int    g_cursor[NN];
__device__ int    g_bsum  [128];
__device__ int    g_boff  [128];
__device__ int    g_esrc  [EE];
__device__ __half g_hsh   [(size_t)NN * DHID];  // (X@W1)*dis, fp16
__device__ float  g_hs2   [NN * DOUT];          // (h1@W2)*dis
__device__ __half g_wthi  [DHID * DIN];         // W1^T hi  [n][k], fp16
__device__ __half g_wtlo  [DHID * DIN];         // W1^T lo  [n][k], fp16 residual
__device__ int    g_is64;

// edge_index may arrive as int64 (reference dtype) or int32 (JAX x64 off).
__device__ __forceinline__ void load_edge(const void* ei, int e, int& s, int& d) {
    if (g_is64) {
        const long long* p = (const long long*)ei;
        s = (int)p[e];
        d = (int)p[(size_t)EE + e];
    } else {
        const int* p = (const int*)ei;
        s = p[e];
        d = p[EE + e];
    }
}

__device__ __forceinline__ uint32_t pack_h2(float a, float b) {
    __half2 h = __floats2half2_rn(a, b);
    return *(uint32_t*)&h;
}

__device__ __forceinline__ uint32_t smem_u32(const void* p) {
    uint32_t a;
    asm("{ .reg .u64 t; cvta.to.shared.u64 t, %1; cvt.u32.u64 %0, t; }"
        : "=r"(a) : "l"(p));
    return a;
}
#define LDSM_X4(r0, r1, r2, r3, addr) \
    asm volatile("ldmatrix.sync.aligned.m8n8.x4.shared.b16 {%0,%1,%2,%3}, [%4];" \
        : "=r"(r0), "=r"(r1), "=r"(r2), "=r"(r3) : "r"(addr))
#define CP16(dst, src) \
    asm volatile("cp.async.ca.shared.global [%0], [%1], 16;" :: "r"(dst), "l"(src))
#define CP_COMMIT() asm volatile("cp.async.commit_group;")
#define CP_WAIT0()  asm volatile("cp.async.wait_group 0;" ::: "memory")

// ===== init: detect idx width + zero degrees + W1 transpose/split (fp16) =====
__global__ void init_kernel(const int* __restrict__ ei32, const float* __restrict__ W1) {
    int idx = blockIdx.x * blockDim.x + threadIdx.x;
    if (idx == 0) {
        int all0 = 1;
        #pragma unroll
        for (int i = 1; i < 64; i += 2) all0 &= (ei32[i] == 0);
        g_is64 = all0;
    }
    if (idx < NN) g_degi[idx] = 0;
    if (idx < DHID * DIN) {
        int n = idx >> 9;
        int k = idx & 511;
        float w = W1[(size_t)k * DHID + n];
        __half h = __float2half_rn(w);
        g_wthi[idx] = h;
        g_wtlo[idx] = __float2half_rn(w - __half2float(h));
    }
}

__global__ void degree_kernel(const void* __restrict__ ei) {
    int e = (blockIdx.x * blockDim.x + threadIdx.x) * 2;
    if (e >= EE) return;
    if (g_is64) {
        const long long* p = (const long long*)ei;
        longlong2 v = *(const longlong2*)(p + EE + e);
        atomicAdd(&g_degi[(int)v.x], 1);
        atomicAdd(&g_degi[(int)v.y], 1);
    } else {
        const int* p = (const int*)ei;
        int2 v = *(const int2*)(p + EE + e);
        atomicAdd(&g_degi[v.x], 1);
        atomicAdd(&g_degi[v.y], 1);
    }
}

__global__ void dis_kernel() {
    int i = blockIdx.x * blockDim.x + threadIdx.x;
    if (i < NN) g_dis[i] = rsqrtf((float)g_degi[i] + 1.0f);
}

__global__ void scan1_kernel() {
    __shared__ int sh[1024];
    int t = threadIdx.x;
    int i = blockIdx.x * 1024 + t;
    int v = (i < NN) ? g_degi[i] : 0;
    sh[t] = v;
    __syncthreads();
    for (int d = 1; d < 1024; d <<= 1) {
        int add = (t >= d) ? sh[t - d] : 0;
        __syncthreads();
        sh[t] += add;
        __syncthreads();
    }
    if (i < NN) g_off[i] = sh[t] - v;
    if (t == 1023) g_bsum[blockIdx.x] = sh[1023];
}
__global__ void scan2_kernel(int nblk) {
    __shared__ int sh[128];
    int t = threadIdx.x;
    int v = (t < nblk) ? g_bsum[t] : 0;
    sh[t] = v;
    __syncthreads();
    for (int d = 1; d < 128; d <<= 1) {
        int add = (t >= d) ? sh[t - d] : 0;
        __syncthreads();
        sh[t] += add;
        __syncthreads();
    }
    if (t < nblk) g_boff[t] = sh[t] - v;
}
__global__ void scan3_kernel() {
    int i = blockIdx.x * blockDim.x + threadIdx.x;
    if (i >= NN) return;
    int o = g_off[i] + g_boff[i >> 10];
    g_off[i] = o;
    g_cursor[i] = o;
}
__global__ void fill_kernel(const void* __restrict__ ei) {
    int e = blockIdx.x * blockDim.x + threadIdx.x;
    if (e >= EE) return;
    int s, d;
    load_edge(ei, e, s, d);
    int pos = atomicAdd(&g_cursor[d], 1);
    g_esrc[pos] = s;
}

// ======================= GEMM1 via mma.sync fp16 (A single, W split) ===============
// CTA: 256(M) x 128(N), 512 threads = 16 warps 4(m) x 4(n); warp tile 64 x 32.
// Taller warp tile: per k16 half, 8 LDSM.x4 feed 32 MMAs (was 6:16) -> LDSM
// wavefronts per output /1.5. fp16 2-pass: A*Whi + A*Wlo. Double-buffered smem,
// one sync per chunk, cp.async B staging, ldmatrix.x4.

#define SPITCH 40
#define OFF_A   0
#define OFF_BHI 10240
#define OFF_BLO 15360
#define BUF_ELEMS 20480
#define BUF_BYTES (BUF_ELEMS * 2)           // 40960
#define GEMM_SMEM_BYTES (2 * BUF_BYTES)     // 81920

__device__ __forceinline__ void mma_f16(float* d, const uint32_t* a, const uint32_t* b) {
    asm volatile(
        "mma.sync.aligned.m16n8k16.row.col.f32.f16.f16.f32 "
        "{%0,%1,%2,%3}, {%4,%5,%6,%7}, {%8,%9}, {%0,%1,%2,%3};"
        : "+f"(d[0]), "+f"(d[1]), "+f"(d[2]), "+f"(d[3])
        : "r"(a[0]), "r"(a[1]), "r"(a[2]), "r"(a[3]), "r"(b[0]), "r"(b[1]));
}

__global__ void __launch_bounds__(512, 1) gemm1_mma_kernel(const float* __restrict__ X) {
    extern __shared__ __half sm[];
    const uint32_t sbase = smem_u32(sm);

    const int tid   = threadIdx.x;
    const int lane  = tid & 31;
    const int wid   = tid >> 5;
    const int warpM = wid & 3;          // *64 m offset
    const int warpN = wid >> 2;         // *32 n offset
    const int g     = lane >> 2;
    const int t     = lane & 3;
    const int mbase = blockIdx.x * 256;

    // A staging: thread -> (row ar, k-half ak), 16 floats -> 16 fp16 (2x STS.128)
    const int ar  = tid >> 1;            // 0..255
    const int ak  = (tid & 1) << 4;      // 0 or 16
    const bool av = (mbase + ar) < NN;
    const float* xrow = X + (size_t)(mbase + ar) * DIN;
    // B staging (cp.async): thread -> (row bn, 16B segment bof); buffer-0 base addrs
    const int bn  = tid >> 2;            // 0..127
    const int bof = (tid & 3) << 3;
    const uint32_t bhi0 = sbase + (uint32_t)(OFF_BHI + bn * SPITCH + bof) * 2;
    const uint32_t blo0 = sbase + (uint32_t)(OFF_BLO + bn * SPITCH + bof) * 2;

    // ldmatrix lane-address components
    const int arow = warpM * 64 + (lane & 15);                       // + mi*16
    const int acol = (lane >> 4) << 3;
    const int brow = warpN * 32 + ((lane >> 4) << 3) + (lane & 7);   // + nb*16
    const int bcol = ((lane >> 3) & 1) << 3;

    float acc[4][4][4];
    #pragma unroll
    for (int mi = 0; mi < 4; mi++)
        #pragma unroll
        for (int ni = 0; ni < 4; ni++)
            #pragma unroll
            for (int q = 0; q < 4; q++) acc[mi][ni][q] = 0.0f;

    // ---- prologue: B chunk 0 via cp.async into buf0; A chunk 0 into regs ----
    float4 xr0, xr1, xr2, xr3;
    xr0 = av ? *(const float4*)(xrow + ak + 0)  : make_float4(0.f, 0.f, 0.f, 0.f);
    xr1 = av ? *(const float4*)(xrow + ak + 4)  : make_float4(0.f, 0.f, 0.f, 0.f);
    xr2 = av ? *(const float4*)(xrow + ak + 8)  : make_float4(0.f, 0.f, 0.f, 0.f);
    xr3 = av ? *(const float4*)(xrow + ak + 12) : make_float4(0.f, 0.f, 0.f, 0.f);
    CP16(bhi0, g_wthi + (size_t)bn * DIN + bof);
    CP16(blo0, g_wtlo + (size_t)bn * DIN + bof);
    CP_COMMIT();

    for (int kc = 0; kc < DIN / 32; kc++) {
        const uint32_t bufe = (uint32_t)(kc & 1) * BUF_ELEMS;
        const uint32_t bufb = bufe * 2;
        __half* pA = sm + bufe + OFF_A;

        // ---- stage A (convert prefetched regs to fp16) with 2x STS.128 ----
        {
            uint4 q0, q1;
            q0.x = pack_h2(xr0.x, xr0.y);
            q0.y = pack_h2(xr0.z, xr0.w);
            q0.z = pack_h2(xr1.x, xr1.y);
            q0.w = pack_h2(xr1.z, xr1.w);
            q1.x = pack_h2(xr2.x, xr2.y);
            q1.y = pack_h2(xr2.z, xr2.w);
            q1.z = pack_h2(xr3.x, xr3.y);
            q1.w = pack_h2(xr3.z, xr3.w);
            const int off = ar * SPITCH + ak;
            *(uint4*)&pA[off]     = q0;
            *(uint4*)&pA[off + 8] = q1;
        }
        // ---- prefetch next chunk's X into regs ----
        if (kc + 1 < DIN / 32) {
            const int k1 = (kc + 1) * 32;
            xr0 = av ? *(const float4*)(xrow + k1 + ak + 0)  : make_float4(0.f, 0.f, 0.f, 0.f);
            xr1 = av ? *(const float4*)(xrow + k1 + ak + 4)  : make_float4(0.f, 0.f, 0.f, 0.f);
            xr2 = av ? *(const float4*)(xrow + k1 + ak + 8)  : make_float4(0.f, 0.f, 0.f, 0.f);
            xr3 = av ? *(const float4*)(xrow + k1 + ak + 12) : make_float4(0.f, 0.f, 0.f, 0.f);
        }
        CP_WAIT0();          // B(kc) resident
        __syncthreads();     // all writes to this buffer visible; prev buffer free

        // ---- issue B(kc+1) into the other buffer (overlaps mma below) ----
        if (kc + 1 < DIN / 32) {
            const int k1 = (kc + 1) * 32;
            const uint32_t ob = (uint32_t)((kc + 1) & 1) * BUF_BYTES;
            CP16(bhi0 + ob, g_wthi + (size_t)bn * DIN + k1 + bof);
            CP16(blo0 + ob, g_wtlo + (size_t)bn * DIN + k1 + bof);
            CP_COMMIT();
        }

        // ---- mma on current buffer: two k16 halves ----
        #pragma unroll
        for (int kh = 0; kh < 2; kh++) {
            const int kk = kh * 16;
            uint32_t a[4][4];
            #pragma unroll
            for (int mi = 0; mi < 4; mi++) {
                const uint32_t ab = sbase + bufb +
                    (uint32_t)((arow + mi * 16) * SPITCH + kk + acol) * 2;
                LDSM_X4(a[mi][0], a[mi][1], a[mi][2], a[mi][3], ab + OFF_A * 2);
            }
            // pass 1: Whi (load 8 b regs, use, then reuse registers for Wlo)
            {
                uint32_t bh[4][2];
                #pragma unroll
                for (int nb = 0; nb < 2; nb++) {
                    const uint32_t bb = sbase + bufb +
                        (uint32_t)((brow + nb * 16) * SPITCH + kk + bcol) * 2;
                    LDSM_X4(bh[2 * nb][0], bh[2 * nb][1],
                            bh[2 * nb + 1][0], bh[2 * nb + 1][1], bb + OFF_BHI * 2);
                }
                #pragma unroll
                for (int mi = 0; mi < 4; mi++)
                    #pragma unroll
                    for (int ni = 0; ni < 4; ni++)
                        mma_f16(acc[mi][ni], a[mi], bh[ni]);
            }
            // pass 2: Wlo
            {
                uint32_t bl[4][2];
                #pragma unroll
                for (int nb = 0; nb < 2; nb++) {
                    const uint32_t bb = sbase + bufb +
                        (uint32_t)((brow + nb * 16) * SPITCH + kk + bcol) * 2;
                    LDSM_X4(bl[2 * nb][0], bl[2 * nb][1],
                            bl[2 * nb + 1][0], bl[2 * nb + 1][1], bb + OFF_BLO * 2);
                }
                #pragma unroll
                for (int mi = 0; mi < 4; mi++)
                    #pragma unroll
                    for (int ni = 0; ni < 4; ni++)
                        mma_f16(acc[mi][ni], a[mi], bl[ni]);
            }
        }
    }

    // ---- epilogue: scale by dis, write g_hsh (fp16) ----
    #pragma unroll
    for (int mi = 0; mi < 4; mi++) {
        const int r0 = mbase + warpM * 64 + mi * 16 + g;
        const int r1 = r0 + 8;
        const float s0 = (r0 < NN) ? g_dis[r0] : 0.0f;
        const float s1 = (r1 < NN) ? g_dis[r1] : 0.0f;
        #pragma unroll
        for (int ni = 0; ni < 4; ni++) {
            const int n = warpN * 32 + ni * 8 + 2 * t;
            if (r0 < NN) {
                __half2 v = __floats2half2_rn(acc[mi][ni][0] * s0, acc[mi][ni][1] * s0);
                *(__half2*)&g_hsh[(size_t)r0 * DHID + n] = v;
            }
            if (r1 < NN) {
                __half2 v = __floats2half2_rn(acc[mi][ni][2] * s1, acc[mi][ni][3] * s1);
                *(__half2*)&g_hsh[(size_t)r1 * DHID + n] = v;
            }
        }
    }
}

// ======== CSR aggregation layer 1 (fp16 gather, MLP8) + relu + fused GEMM2 ========
__global__ void __launch_bounds__(256) agg1_fused_kernel(const float* __restrict__ b1,
                                                         const float* __restrict__ W2) {
    int gw   = (blockIdx.x * blockDim.x + threadIdx.x) >> 5;
    int lane = threadIdx.x & 31;
    if (gw >= NN) return;
    int beg = g_off[gw];
    int end = beg + g_degi[gw];
    const uint2* hs = (const uint2*)g_hsh;

    float4 acc;
    {
        uint2 u = hs[(size_t)gw * 32 + lane]; // self term
        float2 p0 = __half22float2(*(__half2*)&u.x);
        float2 p1 = __half22float2(*(__half2*)&u.y);
        acc.x = p0.x; acc.y = p0.y; acc.z = p1.x; acc.w = p1.y;
    }
    for (int j0 = beg; j0 < end; j0 += 32) {
        int mj = j0 + lane;
        int sj = (mj < end) ? g_esrc[mj] : 0;
        int cnt = min(32, end - j0);
        int u = 0;
        for (; u + 8 <= cnt; u += 8) {
            int si[8];
            #pragma unroll
            for (int q = 0; q < 8; q++) si[q] = __shfl_sync(0xFFFFFFFFu, sj, u + q);
            uint2 uv[8];
            #pragma unroll
            for (int q = 0; q < 8; q++) uv[q] = hs[(size_t)si[q] * 32 + lane];
            #pragma unroll
            for (int q = 0; q < 8; q++) {
                float2 p0 = __half22float2(*(__half2*)&uv[q].x);
                float2 p1 = __half22float2(*(__half2*)&uv[q].y);
                acc.x += p0.x; acc.y += p0.y; acc.z += p1.x; acc.w += p1.y;
            }
        }
        for (; u < cnt; u++) {
            int s = __shfl_sync(0xFFFFFFFFu, sj, u);
            uint2 uv = hs[(size_t)s * 32 + lane];
            float2 p0 = __half22float2(*(__half2*)&uv.x);
            float2 p1 = __half22float2(*(__half2*)&uv.y);
            acc.x += p0.x; acc.y += p0.y; acc.z += p1.x; acc.w += p1.y;
        }
    }
    float sc = g_dis[gw];
    float4 b = ((const float4*)b1)[lane];
    float4 h;
    h.x = fmaxf(acc.x * sc + b.x, 0.f);
    h.y = fmaxf(acc.y * sc + b.y, 0.f);
    h.z = fmaxf(acc.z * sc + b.z, 0.f);
    h.w = fmaxf(acc.w * sc + b.w, 0.f);
    float4 w0 = *(const float4*)(W2 + (4 * lane + 0) * 4);
    float4 w1 = *(const float4*)(W2 + (4 * lane + 1) * 4);
    float4 w2 = *(const float4*)(W2 + (4 * lane + 2) * 4);
    float4 w3 = *(const float4*)(W2 + (4 * lane + 3) * 4);
    float a0 = h.x * w0.x + h.y * w1.x + h.z * w2.x + h.w * w3.x;
    float a1 = h.x * w0.y + h.y * w1.y + h.z * w2.y + h.w * w3.y;
    float a2 = h.x * w0.z + h.y * w1.z + h.z * w2.z + h.w * w3.z;
    float a3 = h.x * w0.w + h.y * w1.w + h.z * w2.w + h.w * w3.w;
    #pragma unroll
    for (int o = 16; o; o >>= 1) {
        a0 += __shfl_xor_sync(0xFFFFFFFFu, a0, o);
        a1 += __shfl_xor_sync(0xFFFFFFFFu, a1, o);
        a2 += __shfl_xor_sync(0xFFFFFFFFu, a2, o);
        a3 += __shfl_xor_sync(0xFFFFFFFFu, a3, o);
    }
    if (lane == 0) {
        float4 v;
        v.x = a0 * sc; v.y = a1 * sc; v.z = a2 * sc; v.w = a3 * sc;
        *((float4*)g_hs2 + gw) = v;
    }
}

// ======================= CSR aggregation, layer 2 (fused bias) =======================
__global__ void agg2_csr_kernel(const float* __restrict__ b2, float* __restrict__ out) {
    int i = blockIdx.x * blockDim.x + threadIdx.x;
    if (i >= NN) return;
    int beg = g_off[i];
    int end = beg + g_degi[i];
    const float4* h4 = (const float4*)g_hs2;
    float4 acc = h4[i];
    int j = beg;
    for (; j + 4 <= end; j += 4) {
        float4 v0 = h4[g_esrc[j]];
        float4 v1 = h4[g_esrc[j + 1]];
        float4 v2 = h4[g_esrc[j + 2]];
        float4 v3 = h4[g_esrc[j + 3]];
        acc.x += (v0.x + v1.x) + (v2.x + v3.x);
        acc.y += (v0.y + v1.y) + (v2.y + v3.y);
        acc.z += (v0.z + v1.z) + (v2.z + v3.z);
        acc.w += (v0.w + v1.w) + (v2.w + v3.w);
    }
    for (; j < end; j++) {
        float4 v = h4[g_esrc[j]];
        acc.x += v.x; acc.y += v.y; acc.z += v.z; acc.w += v.w;
    }
    float s = g_dis[i];
    float4 b = *(const float4*)b2;
    float4 v;
    v.x = acc.x * s + b.x;
    v.y = acc.y * s + b.y;
    v.z = acc.z * s + b.z;
    v.w = acc.w * s + b.w;
    *((float4*)out + i) = v;
}

// ======================= launch =======================
extern "C" void kernel_launch(void* const* d_in, const int* in_sizes, int n_in,
                              void* d_out, int out_size) {
    const float* x  = (const float*)d_in[0];
    const void*  ei = d_in[1];
    const float* W1 = (const float*)d_in[2];
    const float* b1 = (const float*)d_in[3];
    const float* W2 = (const float*)d_in[4];
    const float* b2 = (const float*)d_in[5];
    float* out = (float*)d_out;

    static bool s_init = []() {
        cudaFuncSetAttribute(gemm1_mma_kernel,
                             cudaFuncAttributeMaxDynamicSharedMemorySize, GEMM_SMEM_BYTES);
        return true;
    }();
    (void)s_init;

    const int nblk_scan = (NN + 1023) / 1024;           // 98
    const int nblk_init = (NN + 255) / 256;

    // order: gemm1 sits at launch index 3 so the fixed ncu capture slot profiles it
    init_kernel  <<<nblk_init, 256>>>((const int*)ei, W1);
    degree_kernel<<<(EE / 2 + 255) / 256, 256>>>(ei);
    dis_kernel   <<<(NN + 255) / 256, 256>>>();
    gemm1_mma_kernel<<<(NN + 255) / 256, 512, GEMM_SMEM_BYTES>>>(x);
    scan1_kernel <<<nblk_scan, 1024>>>();
    scan2_kernel <<<1, 128>>>(nblk_scan);
    scan3_kernel <<<(NN + 255) / 256, 256>>>();
    fill_kernel  <<<(EE + 255) / 256, 256>>>(ei);
    agg1_fused_kernel<<<(NN * 32 + 255) / 256, 256>>>(b1, W2);
    agg2_csr_kernel  <<<(NN + 255) / 256, 256>>>(b2, out);
}